// round 1
// baseline (speedup 1.0000x reference)
#include <cuda_runtime.h>
#include <math.h>
#include <stdint.h>

// Problem constants
#define B_SZ   8
#define C_SZ   256
#define H_SZ   64
#define W_SZ   64
#define PIX    4096          // H*W
#define L_TOT  32768         // B*H*W
#define HEADS  4
#define CDIM   32            // head dim per branch (128/4)
#define WIN    256           // window size (positions)
#define NWIN   128           // windows per branch (B*16)
#define SCALE  0.125f        // (256/4)^-0.5
#define LN_EPS 1e-4f

// out tuple layout in d_out (floats)
#define OUT_ELEMS  ((size_t)B_SZ * C_SZ * PIX)          // 8388608
#define ATTN_ELEMS ((size_t)NWIN * HEADS * WIN * WIN)   // 8388608

// Scratch (device globals — no allocation allowed)
__device__ float g_xn[(size_t)B_SZ * C_SZ * PIX];     // LayerNorm out, [b][c][p]
__device__ float g_qkv[(size_t)B_SZ * 3 * C_SZ * PIX]; // qkv, [b][j<768][p]
__device__ float g_xcat[(size_t)B_SZ * C_SZ * PIX];   // attention out, [b][c][p]

// ---------------------------------------------------------------------------
// LayerNorm over C for each pixel. Block = 32 pixels, 256 threads.
// x: [b][c][p], out xn: [b][c][p]
// ---------------------------------------------------------------------------
__global__ void ln_kernel(const float* __restrict__ x,
                          const float* __restrict__ g,
                          const float* __restrict__ be,
                          float* __restrict__ xnT) {
    int px0  = blockIdx.x * 32;          // global pixel index start
    int b    = px0 >> 12;
    int p0   = px0 & (PIX - 1);
    int lane = threadIdx.x & 31;
    int ty   = threadIdx.x >> 5;         // 0..7

    const float* xb = x + (size_t)b * C_SZ * PIX + p0 + lane;
    float v[32];
    float sum = 0.f, sq = 0.f;
#pragma unroll
    for (int i = 0; i < 32; i++) {
        int c = ty + i * 8;
        float t = xb[(size_t)c * PIX];
        v[i] = t;
        sum += t;
        sq  += t * t;
    }
    __shared__ float rs[2][8][32];
    __shared__ float mu_s[32], rstd_s[32];
    rs[0][ty][lane] = sum;
    rs[1][ty][lane] = sq;
    __syncthreads();
    if (ty == 0) {
        float s1 = 0.f, s2 = 0.f;
#pragma unroll
        for (int k = 0; k < 8; k++) { s1 += rs[0][k][lane]; s2 += rs[1][k][lane]; }
        float mu  = s1 * (1.0f / C_SZ);
        float var = s2 * (1.0f / C_SZ) - mu * mu;
        mu_s[lane]   = mu;
        rstd_s[lane] = rsqrtf(var + LN_EPS);
    }
    __syncthreads();
    float mu = mu_s[lane], rstd = rstd_s[lane];
    float* ob = xnT + (size_t)b * C_SZ * PIX + p0 + lane;
#pragma unroll
    for (int i = 0; i < 32; i++) {
        int c = ty + i * 8;
        ob[(size_t)c * PIX] = (v[i] - mu) * rstd * g[c] + be[c];
    }
}

// ---------------------------------------------------------------------------
// Channel-major SGEMM: outT[b][j][p] = sum_c AT[b][c][p] * W[j][c] (+ bias[j])
// Tile 128(l) x 128(j) x 8(k), 256 threads, 8x8 microtiles.
// ---------------------------------------------------------------------------
#define GTM 128
#define GTN 128
#define GTK 8

__global__ void gemm_cm(const float* __restrict__ AT,
                        const float* __restrict__ W,
                        const float* __restrict__ bias,
                        float* __restrict__ outT,
                        int CA, int CO, int hasb) {
    __shared__ float As[GTK][GTM + 4];
    __shared__ float Bs[GTK][GTN + 4];

    int l0 = blockIdx.x * GTM;
    int j0 = blockIdx.y * GTN;
    int b  = l0 >> 12;
    int p0 = l0 & (PIX - 1);

    const float* Abase = AT + (size_t)b * CA * PIX + p0;
    int tid = threadIdx.x;
    int tx  = tid & 15;   // l-quad
    int ty  = tid >> 4;   // j-quad

    float acc[8][8];
#pragma unroll
    for (int i = 0; i < 8; i++)
#pragma unroll
        for (int j = 0; j < 8; j++) acc[i][j] = 0.f;

    for (int c0 = 0; c0 < CA; c0 += GTK) {
        // Load A tile: 8 x 128
        {
            int k = tid >> 5;             // 0..7
            int l = (tid & 31) << 2;      // 0,4,...,124
            float4 v4 = *(const float4*)(Abase + (size_t)(c0 + k) * PIX + l);
            *(float4*)&As[k][l] = v4;
        }
        // Load W tile: 128 j x 8 k, store as Bs[k][j]
        {
            int j = tid >> 1;             // 0..127
            int k = (tid & 1) << 2;       // 0 or 4
            float4 v4 = *(const float4*)(W + (size_t)(j0 + j) * CA + c0 + k);
            Bs[k + 0][j] = v4.x;
            Bs[k + 1][j] = v4.y;
            Bs[k + 2][j] = v4.z;
            Bs[k + 3][j] = v4.w;
        }
        __syncthreads();
#pragma unroll
        for (int k = 0; k < GTK; k++) {
            float a[8], bb[8];
            *(float4*)&a[0]  = *(float4*)&As[k][tx * 8];
            *(float4*)&a[4]  = *(float4*)&As[k][tx * 8 + 4];
            *(float4*)&bb[0] = *(float4*)&Bs[k][ty * 8];
            *(float4*)&bb[4] = *(float4*)&Bs[k][ty * 8 + 4];
#pragma unroll
            for (int jj = 0; jj < 8; jj++)
#pragma unroll
                for (int ii = 0; ii < 8; ii++)
                    acc[jj][ii] += a[ii] * bb[jj];
        }
        __syncthreads();
    }

    // Write out
#pragma unroll
    for (int jj = 0; jj < 8; jj++) {
        int j = j0 + ty * 8 + jj;
        float bv = hasb ? bias[j] : 0.f;
        float* orow = outT + (size_t)b * CO * PIX + (size_t)j * PIX + p0 + tx * 8;
        float4 v0 = make_float4(acc[jj][0] + bv, acc[jj][1] + bv, acc[jj][2] + bv, acc[jj][3] + bv);
        float4 v1 = make_float4(acc[jj][4] + bv, acc[jj][5] + bv, acc[jj][6] + bv, acc[jj][7] + bv);
        *(float4*)(orow)     = v0;
        *(float4*)(orow + 4) = v1;
    }
}

// ---------------------------------------------------------------------------
// Stripe-window attention + LePE.
// grid: (128 windows, 4 heads, 2 branches); 256 threads = 256 positions.
// qkvT: [b][j<768][p].  xcat: [b][c][p].  out: d_out (attn regions).
// dynamic smem: ks[32][256], vs[32][256]  (transposed: [cc][s])
// ---------------------------------------------------------------------------
__global__ void attn_kernel(const float* __restrict__ qkvT,
                            const float* __restrict__ lw1,
                            const float* __restrict__ lb1,
                            const float* __restrict__ lw2,
                            const float* __restrict__ lb2,
                            float* __restrict__ xcat,
                            float* __restrict__ dout) {
    int br   = blockIdx.z;           // branch
    int hd   = blockIdx.y;           // head
    int widx = blockIdx.x;           // 0..127 : b*16 + wg
    int b    = widx >> 4;
    int wg   = widx & 15;
    int s    = threadIdx.x;          // window position

    int hsp, wsp, p, rr0, cc0;
    if (br == 0) {                   // vertical stripes: 64 rows x 4 cols
        hsp = 64; wsp = 4;
        rr0 = s >> 2; cc0 = s & 3;
        p = rr0 * W_SZ + wg * 4 + cc0;
    } else {                         // horizontal stripes: 4 rows x 64 cols
        hsp = 4; wsp = 64;
        rr0 = s >> 6; cc0 = s & 63;
        p = (wg * 4 + rr0) * W_SZ + cc0;
    }
    const float* lw = br ? lw2 : lw1;
    const float* lb = br ? lb2 : lb1;

    extern __shared__ float sm[];
    float* ks = sm;                  // [32][256]
    float* vs = sm + 32 * WIN;       // [32][256]
    __shared__ float lwsh[32][9];
    __shared__ float lbsh[32];

    size_t base = (size_t)b * 3 * C_SZ * PIX;
    float qr[32];
#pragma unroll
    for (int cc = 0; cc < 32; cc++) {
        int ch = br * 128 + cc * 4 + hd;
        qr[cc]           = qkvT[base + (size_t)ch * PIX + p] * SCALE;
        ks[cc * WIN + s] = qkvT[base + (size_t)(C_SZ + ch) * PIX + p];
        vs[cc * WIN + s] = qkvT[base + (size_t)(2 * C_SZ + ch) * PIX + p];
    }
    // LePE weights/bias for this head
    for (int i = s; i < 32 * 9; i += 256) {
        int cc = i / 9, kk = i % 9;
        lwsh[cc][kk] = lw[(size_t)(cc * 4 + hd) * 9 + kk];
    }
    if (s < 32) lbsh[s] = lb[s * 4 + hd];
    __syncthreads();

    // attn row for this (branch, window, head, position)
    size_t arow = OUT_ELEMS + (size_t)br * ATTN_ELEMS
                + ((size_t)(widx * HEADS + hd) * WIN + s) * WIN;

    // pass 1: raw scores, track max
    float mx = -1e30f;
    for (int j = 0; j < WIN; j++) {
        float acc = 0.f;
#pragma unroll
        for (int cc = 0; cc < 32; cc++) acc += qr[cc] * ks[cc * WIN + j];
        dout[arow + j] = acc;
        mx = fmaxf(mx, acc);
    }
    // pass 2: exp + unnormalized o accumulation
    float o[32];
#pragma unroll
    for (int cc = 0; cc < 32; cc++) o[cc] = 0.f;
    float sum = 0.f;
    for (int j = 0; j < WIN; j++) {
        float e = __expf(dout[arow + j] - mx);
        sum += e;
        dout[arow + j] = e;
#pragma unroll
        for (int cc = 0; cc < 32; cc++) o[cc] += e * vs[cc * WIN + j];
    }
    float rinv = 1.0f / sum;
    // pass 3: normalize attn in global
    for (int j = 0; j < WIN; j += 4) {
        float4 v4 = *(float4*)&dout[arow + j];
        v4.x *= rinv; v4.y *= rinv; v4.z *= rinv; v4.w *= rinv;
        *(float4*)&dout[arow + j] = v4;
    }

    // LePE (depthwise 3x3 within the stripe image, SAME zero pad) + write
    size_t obase = (size_t)b * C_SZ * PIX + p;
#pragma unroll
    for (int cc = 0; cc < 32; cc++) {
        float acc = lbsh[cc];
#pragma unroll
        for (int ky = 0; ky < 3; ky++) {
            int rr = rr0 + ky - 1;
            if (rr < 0 || rr >= hsp) continue;
#pragma unroll
            for (int kx = 0; kx < 3; kx++) {
                int cx = cc0 + kx - 1;
                if (cx < 0 || cx >= wsp) continue;
                acc += lwsh[cc][ky * 3 + kx] * vs[cc * WIN + rr * wsp + cx];
            }
        }
        int ch = br * 128 + cc * 4 + hd;
        xcat[obase + (size_t)ch * PIX] = o[cc] * rinv + acc;
    }
}

// ---------------------------------------------------------------------------
extern "C" void kernel_launch(void* const* d_in, const int* in_sizes, int n_in,
                              void* d_out, int out_size) {
    const float* x       = (const float*)d_in[0];
    const float* ln_g    = (const float*)d_in[1];
    const float* ln_b    = (const float*)d_in[2];
    const float* w_qkv   = (const float*)d_in[3];
    const float* proj_w  = (const float*)d_in[4];
    const float* proj_b  = (const float*)d_in[5];
    const float* lepe_w1 = (const float*)d_in[6];
    const float* lepe_b1 = (const float*)d_in[7];
    const float* lepe_w2 = (const float*)d_in[8];
    const float* lepe_b2 = (const float*)d_in[9];
    float* out = (float*)d_out;

    float *xn, *qkv, *xcat;
    cudaGetSymbolAddress((void**)&xn,   g_xn);
    cudaGetSymbolAddress((void**)&qkv,  g_qkv);
    cudaGetSymbolAddress((void**)&xcat, g_xcat);

    // 1. LayerNorm
    ln_kernel<<<L_TOT / 32, 256>>>(x, ln_g, ln_b, xn);

    // 2. QKV GEMM: [768 x 256] x xn -> qkv
    {
        dim3 grid(L_TOT / GTM, (3 * C_SZ) / GTN);
        gemm_cm<<<grid, 256>>>(xn, w_qkv, nullptr, qkv, C_SZ, 3 * C_SZ, 0);
    }

    // 3. Attention + LePE (both branches)
    {
        static int smem_set = 0;
        size_t dyn = (size_t)2 * 32 * WIN * sizeof(float);   // 64 KB
        cudaFuncSetAttribute(attn_kernel, cudaFuncAttributeMaxDynamicSharedMemorySize,
                             (int)dyn);
        (void)smem_set;
        dim3 grid(NWIN, HEADS, 2);
        attn_kernel<<<grid, 256, dyn>>>(qkv, lepe_w1, lepe_b1, lepe_w2, lepe_b2,
                                        xcat, out);
    }

    // 4. Projection GEMM + bias -> d_out[0 : OUT_ELEMS]
    {
        dim3 grid(L_TOT / GTM, C_SZ / GTN);
        gemm_cm<<<grid, 256>>>(xcat, proj_w, proj_b, out, C_SZ, C_SZ, 1);
    }
    (void)in_sizes; (void)n_in; (void)out_size;
}

// round 2
// speedup vs baseline: 4.1284x; 4.1284x over previous
#include <cuda_runtime.h>
#include <math.h>
#include <stdint.h>

// Problem constants
#define B_SZ   8
#define C_SZ   256
#define H_SZ   64
#define W_SZ   64
#define PIX    4096          // H*W
#define L_TOT  32768         // B*H*W
#define HEADS  4
#define WIN    256           // window size (positions)
#define NWIN   128           // windows per branch (B*16)
#define SCALE  0.125f        // (256/4)^-0.5
#define LN_EPS 1e-4f

#define OUT_ELEMS  ((size_t)B_SZ * C_SZ * PIX)          // 8388608
#define ATTN_ELEMS ((size_t)NWIN * HEADS * WIN * WIN)   // 8388608

// Scratch (device globals — no allocation allowed)
__device__ float g_xn[(size_t)B_SZ * C_SZ * PIX];       // LayerNorm out, [b][c][p]
__device__ float g_qkv[(size_t)B_SZ * 3 * C_SZ * PIX];  // qkv, [b][j<768][p]
__device__ float g_xcat[(size_t)B_SZ * C_SZ * PIX];     // attention out, [b][c][p]

// ---------------------------------------------------------------------------
// LayerNorm over C for each pixel. Block = 32 pixels, 256 threads.
// ---------------------------------------------------------------------------
__global__ void ln_kernel(const float* __restrict__ x,
                          const float* __restrict__ g,
                          const float* __restrict__ be,
                          float* __restrict__ xnT) {
    int px0  = blockIdx.x * 32;
    int b    = px0 >> 12;
    int p0   = px0 & (PIX - 1);
    int lane = threadIdx.x & 31;
    int ty   = threadIdx.x >> 5;

    const float* xb = x + (size_t)b * C_SZ * PIX + p0 + lane;
    float v[32];
    float sum = 0.f, sq = 0.f;
#pragma unroll
    for (int i = 0; i < 32; i++) {
        int c = ty + i * 8;
        float t = xb[(size_t)c * PIX];
        v[i] = t;
        sum += t;
        sq  += t * t;
    }
    __shared__ float rs[2][8][32];
    __shared__ float mu_s[32], rstd_s[32];
    rs[0][ty][lane] = sum;
    rs[1][ty][lane] = sq;
    __syncthreads();
    if (ty == 0) {
        float s1 = 0.f, s2 = 0.f;
#pragma unroll
        for (int k = 0; k < 8; k++) { s1 += rs[0][k][lane]; s2 += rs[1][k][lane]; }
        float mu  = s1 * (1.0f / C_SZ);
        float var = s2 * (1.0f / C_SZ) - mu * mu;
        mu_s[lane]   = mu;
        rstd_s[lane] = rsqrtf(var + LN_EPS);
    }
    __syncthreads();
    float mu = mu_s[lane], rstd = rstd_s[lane];
    float* ob = xnT + (size_t)b * C_SZ * PIX + p0 + lane;
#pragma unroll
    for (int i = 0; i < 32; i++) {
        int c = ty + i * 8;
        ob[(size_t)c * PIX] = (v[i] - mu) * rstd * g[c] + be[c];
    }
}

// ---------------------------------------------------------------------------
// Channel-major SGEMM: outT[b][j][p] = sum_c AT[b][c][p] * W[j][c] (+ bias[j])
// ---------------------------------------------------------------------------
#define GTM 128
#define GTN 128
#define GTK 8

__global__ void gemm_cm(const float* __restrict__ AT,
                        const float* __restrict__ W,
                        const float* __restrict__ bias,
                        float* __restrict__ outT,
                        int CA, int CO, int hasb) {
    __shared__ float As[GTK][GTM + 4];
    __shared__ float Bs[GTK][GTN + 4];

    int l0 = blockIdx.x * GTM;
    int j0 = blockIdx.y * GTN;
    int b  = l0 >> 12;
    int p0 = l0 & (PIX - 1);

    const float* Abase = AT + (size_t)b * CA * PIX + p0;
    int tid = threadIdx.x;
    int tx  = tid & 15;
    int ty  = tid >> 4;

    float acc[8][8];
#pragma unroll
    for (int i = 0; i < 8; i++)
#pragma unroll
        for (int j = 0; j < 8; j++) acc[i][j] = 0.f;

    for (int c0 = 0; c0 < CA; c0 += GTK) {
        {
            int k = tid >> 5;
            int l = (tid & 31) << 2;
            float4 v4 = *(const float4*)(Abase + (size_t)(c0 + k) * PIX + l);
            *(float4*)&As[k][l] = v4;
        }
        {
            int j = tid >> 1;
            int k = (tid & 1) << 2;
            float4 v4 = *(const float4*)(W + (size_t)(j0 + j) * CA + c0 + k);
            Bs[k + 0][j] = v4.x;
            Bs[k + 1][j] = v4.y;
            Bs[k + 2][j] = v4.z;
            Bs[k + 3][j] = v4.w;
        }
        __syncthreads();
#pragma unroll
        for (int k = 0; k < GTK; k++) {
            float a[8], bb[8];
            *(float4*)&a[0]  = *(float4*)&As[k][tx * 8];
            *(float4*)&a[4]  = *(float4*)&As[k][tx * 8 + 4];
            *(float4*)&bb[0] = *(float4*)&Bs[k][ty * 8];
            *(float4*)&bb[4] = *(float4*)&Bs[k][ty * 8 + 4];
#pragma unroll
            for (int jj = 0; jj < 8; jj++)
#pragma unroll
                for (int ii = 0; ii < 8; ii++)
                    acc[jj][ii] += a[ii] * bb[jj];
        }
        __syncthreads();
    }

#pragma unroll
    for (int jj = 0; jj < 8; jj++) {
        int j = j0 + ty * 8 + jj;
        float bv = hasb ? bias[j] : 0.f;
        float* orow = outT + (size_t)b * CO * PIX + (size_t)j * PIX + p0 + tx * 8;
        float4 v0 = make_float4(acc[jj][0] + bv, acc[jj][1] + bv, acc[jj][2] + bv, acc[jj][3] + bv);
        float4 v1 = make_float4(acc[jj][4] + bv, acc[jj][5] + bv, acc[jj][6] + bv, acc[jj][7] + bv);
        *(float4*)(orow)     = v0;
        *(float4*)(orow + 4) = v1;
    }
}

// ---------------------------------------------------------------------------
// Stripe-window attention + LePE, v2.
// grid: (128 windows, 4 heads, 2 branches); 256 threads = 256 positions.
// Single compute pass (no max subtraction needed: scores are O(1)):
//   scores -> exp -> row-sum & PV accumulate, e staged via smem tile and
//   written coalesced unnormalized; then in-kernel coalesced normalize pass.
// dyn smem: ks[32*256] vs[32*256] ps[256*33] rs[256]  (~98KB)
// ---------------------------------------------------------------------------
#define PST 33   // ps row stride (pad)

__global__ __launch_bounds__(256, 2)
void attn_kernel(const float* __restrict__ qkvT,
                 const float* __restrict__ lw1,
                 const float* __restrict__ lb1,
                 const float* __restrict__ lw2,
                 const float* __restrict__ lb2,
                 float* __restrict__ xcat,
                 float* __restrict__ dout) {
    int br   = blockIdx.z;
    int hd   = blockIdx.y;
    int widx = blockIdx.x;
    int b    = widx >> 4;
    int wg   = widx & 15;
    int s    = threadIdx.x;

    int hsp, wsp, p, rr0, cc0;
    if (br == 0) {                   // vertical stripes: 64 rows x 4 cols
        hsp = 64; wsp = 4;
        rr0 = s >> 2; cc0 = s & 3;
        p = rr0 * W_SZ + wg * 4 + cc0;
    } else {                         // horizontal stripes: 4 rows x 64 cols
        hsp = 4; wsp = 64;
        rr0 = s >> 6; cc0 = s & 63;
        p = (wg * 4 + rr0) * W_SZ + cc0;
    }
    const float* lw = br ? lw2 : lw1;
    const float* lb = br ? lb2 : lb1;

    extern __shared__ float sm[];
    float* ks = sm;                     // [32][256]
    float* vs = sm + 32 * WIN;          // [32][256]
    float* ps = sm + 64 * WIN;          // [256][PST]
    float* rsum = ps + 256 * PST;       // [256] row 1/sum
    __shared__ float lwsh[32][9];
    __shared__ float lbsh[32];

    size_t base = (size_t)b * 3 * C_SZ * PIX;
    float q[32];
#pragma unroll
    for (int cc = 0; cc < 32; cc++) {
        int ch = br * 128 + cc * 4 + hd;
        q[cc]            = qkvT[base + (size_t)ch * PIX + p] * SCALE;
        ks[cc * WIN + s] = qkvT[base + (size_t)(C_SZ + ch) * PIX + p];
        vs[cc * WIN + s] = qkvT[base + (size_t)(2 * C_SZ + ch) * PIX + p];
    }
    for (int i = s; i < 32 * 9; i += 256) {
        int cc = i / 9, kk = i % 9;
        lwsh[cc][kk] = lw[(size_t)(cc * 4 + hd) * 9 + kk];
    }
    if (s < 32) lbsh[s] = lb[s * 4 + hd];
    __syncthreads();

    size_t abase = OUT_ELEMS + (size_t)br * ATTN_ELEMS
                 + (size_t)(widx * HEADS + hd) * WIN * WIN;

    float o[32];
#pragma unroll
    for (int cc = 0; cc < 32; cc++) o[cc] = 0.f;
    float sum = 0.f;

    // ---- compute pass over col chunks of 32 ----
    for (int c0 = 0; c0 < WIN; c0 += 32) {
        for (int j0 = 0; j0 < 32; j0 += 4) {
            float s0 = 0.f, s1 = 0.f, s2 = 0.f, s3 = 0.f;
            const float* kp = ks + c0 + j0;
#pragma unroll
            for (int cc = 0; cc < 32; cc++) {
                float4 kv = *(const float4*)(kp + cc * WIN);  // uniform bcast
                s0 += q[cc] * kv.x;
                s1 += q[cc] * kv.y;
                s2 += q[cc] * kv.z;
                s3 += q[cc] * kv.w;
            }
            float e0 = __expf(s0), e1 = __expf(s1), e2 = __expf(s2), e3 = __expf(s3);
            sum += (e0 + e1) + (e2 + e3);
            ps[s * PST + j0 + 0] = e0;
            ps[s * PST + j0 + 1] = e1;
            ps[s * PST + j0 + 2] = e2;
            ps[s * PST + j0 + 3] = e3;
            const float* vp = vs + c0 + j0;
#pragma unroll
            for (int cc = 0; cc < 32; cc++) {
                float4 vv = *(const float4*)(vp + cc * WIN);  // uniform bcast
                o[cc] += e0 * vv.x + e1 * vv.y + e2 * vv.z + e3 * vv.w;
            }
        }
        __syncthreads();
        // coalesced write of unnormalized e tile (256 rows x 32 cols)
#pragma unroll 8
        for (int k = 0; k < 32; k++) {
            int idx = s + k * 256;
            int row = idx >> 5, col = idx & 31;
            dout[abase + (size_t)row * WIN + c0 + col] = ps[row * PST + col];
        }
        __syncthreads();
    }

    float rinv = 1.0f / sum;
    rsum[s] = rinv;

    // ---- LePE + attention output to xcat ----
    size_t obase = (size_t)b * C_SZ * PIX + p;
#pragma unroll
    for (int cc = 0; cc < 32; cc++) {
        float acc = lbsh[cc];
#pragma unroll
        for (int ky = 0; ky < 3; ky++) {
            int rr = rr0 + ky - 1;
            if (rr < 0 || rr >= hsp) continue;
#pragma unroll
            for (int kx = 0; kx < 3; kx++) {
                int cx = cc0 + kx - 1;
                if (cx < 0 || cx >= wsp) continue;
                acc += lwsh[cc][ky * 3 + kx] * vs[cc * WIN + rr * wsp + cx];
            }
        }
        int ch = br * 128 + cc * 4 + hd;
        xcat[obase + (size_t)ch * PIX] = o[cc] * rinv + acc;
    }
    __syncthreads();

    // ---- normalize pass over this block's attn region (L2-resident) ----
    float4* ap = (float4*)(dout + abase);
#pragma unroll 4
    for (int k = 0; k < 64; k++) {
        int fidx = s + k * 256;          // float4 index, 0..16383
        float r = rsum[fidx >> 6];       // row = fidx*4 >> 8
        float4 v = ap[fidx];
        v.x *= r; v.y *= r; v.z *= r; v.w *= r;
        ap[fidx] = v;
    }
}

// ---------------------------------------------------------------------------
extern "C" void kernel_launch(void* const* d_in, const int* in_sizes, int n_in,
                              void* d_out, int out_size) {
    const float* x       = (const float*)d_in[0];
    const float* ln_g    = (const float*)d_in[1];
    const float* ln_b    = (const float*)d_in[2];
    const float* w_qkv   = (const float*)d_in[3];
    const float* proj_w  = (const float*)d_in[4];
    const float* proj_b  = (const float*)d_in[5];
    const float* lepe_w1 = (const float*)d_in[6];
    const float* lepe_b1 = (const float*)d_in[7];
    const float* lepe_w2 = (const float*)d_in[8];
    const float* lepe_b2 = (const float*)d_in[9];
    float* out = (float*)d_out;

    float *xn, *qkv, *xcat;
    cudaGetSymbolAddress((void**)&xn,   g_xn);
    cudaGetSymbolAddress((void**)&qkv,  g_qkv);
    cudaGetSymbolAddress((void**)&xcat, g_xcat);

    // 1. LayerNorm
    ln_kernel<<<L_TOT / 32, 256>>>(x, ln_g, ln_b, xn);

    // 2. QKV GEMM
    {
        dim3 grid(L_TOT / GTM, (3 * C_SZ) / GTN);
        gemm_cm<<<grid, 256>>>(xn, w_qkv, nullptr, qkv, C_SZ, 3 * C_SZ, 0);
    }

    // 3. Attention + LePE (both branches)
    {
        size_t dyn = (size_t)(64 * WIN + 256 * PST + 256) * sizeof(float);
        cudaFuncSetAttribute(attn_kernel, cudaFuncAttributeMaxDynamicSharedMemorySize,
                             (int)dyn);
        dim3 grid(NWIN, HEADS, 2);
        attn_kernel<<<grid, 256, dyn>>>(qkv, lepe_w1, lepe_b1, lepe_w2, lepe_b2,
                                        xcat, out);
    }

    // 4. Projection GEMM + bias -> d_out[0 : OUT_ELEMS]
    {
        dim3 grid(L_TOT / GTM, C_SZ / GTN);
        gemm_cm<<<grid, 256>>>(xcat, proj_w, proj_b, out, C_SZ, C_SZ, 1);
    }
    (void)in_sizes; (void)n_in; (void)out_size;
}

// round 3
// speedup vs baseline: 5.9877x; 1.4503x over previous
#include <cuda_runtime.h>
#include <math.h>
#include <stdint.h>

// Problem constants
#define B_SZ   8
#define C_SZ   256
#define H_SZ   64
#define W_SZ   64
#define PIX    4096          // H*W
#define L_TOT  32768         // B*H*W
#define HEADS  4
#define WIN    256           // window size (positions)
#define NWIN   128           // windows per branch (B*16)
#define SCALE  0.125f        // (256/4)^-0.5
#define LN_EPS 1e-4f

#define OUT_ELEMS  ((size_t)B_SZ * C_SZ * PIX)          // 8388608
#define ATTN_ELEMS ((size_t)NWIN * HEADS * WIN * WIN)   // 8388608

// Scratch (device globals — no allocation allowed)
__device__ float g_xn[(size_t)B_SZ * C_SZ * PIX];       // LayerNorm out, [b][c][p]
__device__ float g_qkv[(size_t)B_SZ * 3 * C_SZ * PIX];  // qkv, [b][j<768][p]
__device__ float g_xcat[(size_t)B_SZ * C_SZ * PIX];     // attention out, [b][c][p]

// ---------------------------------------------------------------------------
__device__ __forceinline__ uint32_t f2tf(float f) {
    uint32_t r;
    asm("cvt.rna.tf32.f32 %0, %1;" : "=r"(r) : "f"(f));
    return r;
}

__device__ __forceinline__ void mma_tf32(float* d, const uint32_t* a, const uint32_t* b) {
    asm("mma.sync.aligned.m16n8k8.row.col.f32.tf32.tf32.f32 "
        "{%0,%1,%2,%3},{%4,%5,%6,%7},{%8,%9},{%0,%1,%2,%3};"
        : "+f"(d[0]), "+f"(d[1]), "+f"(d[2]), "+f"(d[3])
        : "r"(a[0]), "r"(a[1]), "r"(a[2]), "r"(a[3]), "r"(b[0]), "r"(b[1]));
}

// ---------------------------------------------------------------------------
// LayerNorm over C for each pixel. Block = 32 pixels, 256 threads.
// ---------------------------------------------------------------------------
__global__ void ln_kernel(const float* __restrict__ x,
                          const float* __restrict__ g,
                          const float* __restrict__ be,
                          float* __restrict__ xnT) {
    int px0  = blockIdx.x * 32;
    int b    = px0 >> 12;
    int p0   = px0 & (PIX - 1);
    int lane = threadIdx.x & 31;
    int ty   = threadIdx.x >> 5;

    const float* xb = x + (size_t)b * C_SZ * PIX + p0 + lane;
    float v[32];
    float sum = 0.f, sq = 0.f;
#pragma unroll
    for (int i = 0; i < 32; i++) {
        int c = ty + i * 8;
        float t = xb[(size_t)c * PIX];
        v[i] = t;
        sum += t;
        sq  += t * t;
    }
    __shared__ float rs[2][8][32];
    __shared__ float mu_s[32], rstd_s[32];
    rs[0][ty][lane] = sum;
    rs[1][ty][lane] = sq;
    __syncthreads();
    if (ty == 0) {
        float s1 = 0.f, s2 = 0.f;
#pragma unroll
        for (int k = 0; k < 8; k++) { s1 += rs[0][k][lane]; s2 += rs[1][k][lane]; }
        float mu  = s1 * (1.0f / C_SZ);
        float var = s2 * (1.0f / C_SZ) - mu * mu;
        mu_s[lane]   = mu;
        rstd_s[lane] = rsqrtf(var + LN_EPS);
    }
    __syncthreads();
    float mu = mu_s[lane], rstd = rstd_s[lane];
    float* ob = xnT + (size_t)b * C_SZ * PIX + p0 + lane;
#pragma unroll
    for (int i = 0; i < 32; i++) {
        int c = ty + i * 8;
        ob[(size_t)c * PIX] = (v[i] - mu) * rstd * g[c] + be[c];
    }
}

// ---------------------------------------------------------------------------
// tf32 tensor-core GEMM: outT[b][j][p] = sum_c AT[b][c][p] * W[j][c] (+bias)
// M = j (weights as mma A, row-major), N = p (activations as mma B, col-major)
// Block tile 128(M) x 128(N), K chunks of 32. 8 warps, warp tile 64x32.
// ---------------------------------------------------------------------------
#define ASTR 36    // A smem row stride (words): bank = 4m + k -> conflict-free
#define BSTR 132   // B smem row stride (words): bank = 4k + n -> conflict-free

__global__ __launch_bounds__(256, 2)
void gemm_tf32(const float* __restrict__ AT,
               const float* __restrict__ W,
               const float* __restrict__ bias,
               float* __restrict__ outT,
               int CA, int CO, int hasb) {
    __shared__ uint32_t As[128 * ASTR];   // [m][k]  (W tile, tf32)
    __shared__ uint32_t Bs[32 * BSTR];    // [k][n]  (activation tile, tf32)

    int tid = threadIdx.x;
    int l0  = blockIdx.x * 128;
    int j0  = blockIdx.y * 128;
    int b   = l0 >> 12;
    int p0  = l0 & (PIX - 1);

    const float* Ab = AT + (size_t)b * CA * PIX + p0;
    int lane = tid & 31;
    int wid  = tid >> 5;
    int wm   = wid & 1;        // 0..1  -> M offset 64*wm
    int wn   = wid >> 1;       // 0..3  -> N offset 32*wn

    // loader maps (both STS conflict-free per 8-lane phase, LDG coalesced)
    int aj  = tid >> 1;          // W row within tile (0..127)
    int ac  = (tid & 1) * 16;    // k offset (0 or 16)
    int bk  = tid >> 3;          // activation k row (0..31)
    int bn7 = tid & 7;           // n group

    float d[4][4][4];
#pragma unroll
    for (int mt = 0; mt < 4; mt++)
#pragma unroll
        for (int nt = 0; nt < 4; nt++)
#pragma unroll
            for (int i = 0; i < 4; i++) d[mt][nt][i] = 0.f;

    for (int c0 = 0; c0 < CA; c0 += 32) {
        // ---- load W tile -> As[m][k] (tf32) ----
        const float* wrow = W + (size_t)(j0 + aj) * CA + c0 + ac;
#pragma unroll
        for (int i = 0; i < 4; i++) {
            float4 v = *(const float4*)(wrow + 4 * i);
            uint4 u = make_uint4(f2tf(v.x), f2tf(v.y), f2tf(v.z), f2tf(v.w));
            *(uint4*)&As[aj * ASTR + ac + 4 * i] = u;
        }
        // ---- load activation tile -> Bs[k][n] (tf32) ----
        const float* arow = Ab + (size_t)(c0 + bk) * PIX;
#pragma unroll
        for (int i = 0; i < 4; i++) {
            int nb = (bn7 + 8 * i) * 4;
            float4 v = *(const float4*)(arow + nb);
            uint4 u = make_uint4(f2tf(v.x), f2tf(v.y), f2tf(v.z), f2tf(v.w));
            *(uint4*)&Bs[bk * BSTR + nb] = u;
        }
        __syncthreads();

#pragma unroll
        for (int ks = 0; ks < 4; ks++) {
            int kk = ks * 8 + (lane & 3);
            uint32_t afr[4][4], bfr[4][2];
#pragma unroll
            for (int mt = 0; mt < 4; mt++) {
                int m = wm * 64 + mt * 16 + (lane >> 2);
                afr[mt][0] = As[m * ASTR + kk];
                afr[mt][1] = As[(m + 8) * ASTR + kk];
                afr[mt][2] = As[m * ASTR + kk + 4];
                afr[mt][3] = As[(m + 8) * ASTR + kk + 4];
            }
#pragma unroll
            for (int nt = 0; nt < 4; nt++) {
                int n = wn * 32 + nt * 8 + (lane >> 2);
                bfr[nt][0] = Bs[kk * BSTR + n];
                bfr[nt][1] = Bs[(kk + 4) * BSTR + n];
            }
#pragma unroll
            for (int mt = 0; mt < 4; mt++)
#pragma unroll
                for (int nt = 0; nt < 4; nt++)
                    mma_tf32(d[mt][nt], afr[mt], bfr[nt]);
        }
        __syncthreads();
    }

    // ---- epilogue ----
    float* obase = outT + (size_t)b * CO * PIX;
#pragma unroll
    for (int mt = 0; mt < 4; mt++) {
        int j = j0 + wm * 64 + mt * 16 + (lane >> 2);
        float bv0 = hasb ? bias[j]     : 0.f;
        float bv1 = hasb ? bias[j + 8] : 0.f;
#pragma unroll
        for (int nt = 0; nt < 4; nt++) {
            int p = p0 + wn * 32 + nt * 8 + (lane & 3) * 2;
            float* o = obase + (size_t)j * PIX + p;
            float2 v0 = make_float2(d[mt][nt][0] + bv0, d[mt][nt][1] + bv0);
            float2 v1 = make_float2(d[mt][nt][2] + bv1, d[mt][nt][3] + bv1);
            *(float2*)o = v0;
            *(float2*)(o + 8 * PIX) = v1;
        }
    }
}

// ---------------------------------------------------------------------------
// Stripe-window attention + LePE (unchanged from round 2).
// ---------------------------------------------------------------------------
#define PST 33

__global__ __launch_bounds__(256, 2)
void attn_kernel(const float* __restrict__ qkvT,
                 const float* __restrict__ lw1,
                 const float* __restrict__ lb1,
                 const float* __restrict__ lw2,
                 const float* __restrict__ lb2,
                 float* __restrict__ xcat,
                 float* __restrict__ dout) {
    int br   = blockIdx.z;
    int hd   = blockIdx.y;
    int widx = blockIdx.x;
    int b    = widx >> 4;
    int wg   = widx & 15;
    int s    = threadIdx.x;

    int hsp, wsp, p, rr0, cc0;
    if (br == 0) {
        hsp = 64; wsp = 4;
        rr0 = s >> 2; cc0 = s & 3;
        p = rr0 * W_SZ + wg * 4 + cc0;
    } else {
        hsp = 4; wsp = 64;
        rr0 = s >> 6; cc0 = s & 63;
        p = (wg * 4 + rr0) * W_SZ + cc0;
    }
    const float* lw = br ? lw2 : lw1;
    const float* lb = br ? lb2 : lb1;

    extern __shared__ float sm[];
    float* ks = sm;                     // [32][256]
    float* vs = sm + 32 * WIN;          // [32][256]
    float* ps = sm + 64 * WIN;          // [256][PST]
    float* rsum = ps + 256 * PST;       // [256]
    __shared__ float lwsh[32][9];
    __shared__ float lbsh[32];

    size_t base = (size_t)b * 3 * C_SZ * PIX;
    float q[32];
#pragma unroll
    for (int cc = 0; cc < 32; cc++) {
        int ch = br * 128 + cc * 4 + hd;
        q[cc]            = qkvT[base + (size_t)ch * PIX + p] * SCALE;
        ks[cc * WIN + s] = qkvT[base + (size_t)(C_SZ + ch) * PIX + p];
        vs[cc * WIN + s] = qkvT[base + (size_t)(2 * C_SZ + ch) * PIX + p];
    }
    for (int i = s; i < 32 * 9; i += 256) {
        int cc = i / 9, kk = i % 9;
        lwsh[cc][kk] = lw[(size_t)(cc * 4 + hd) * 9 + kk];
    }
    if (s < 32) lbsh[s] = lb[s * 4 + hd];
    __syncthreads();

    size_t abase = OUT_ELEMS + (size_t)br * ATTN_ELEMS
                 + (size_t)(widx * HEADS + hd) * WIN * WIN;

    float o[32];
#pragma unroll
    for (int cc = 0; cc < 32; cc++) o[cc] = 0.f;
    float sum = 0.f;

    for (int c0 = 0; c0 < WIN; c0 += 32) {
        for (int j0 = 0; j0 < 32; j0 += 4) {
            float s0 = 0.f, s1 = 0.f, s2 = 0.f, s3 = 0.f;
            const float* kp = ks + c0 + j0;
#pragma unroll
            for (int cc = 0; cc < 32; cc++) {
                float4 kv = *(const float4*)(kp + cc * WIN);
                s0 += q[cc] * kv.x;
                s1 += q[cc] * kv.y;
                s2 += q[cc] * kv.z;
                s3 += q[cc] * kv.w;
            }
            float e0 = __expf(s0), e1 = __expf(s1), e2 = __expf(s2), e3 = __expf(s3);
            sum += (e0 + e1) + (e2 + e3);
            ps[s * PST + j0 + 0] = e0;
            ps[s * PST + j0 + 1] = e1;
            ps[s * PST + j0 + 2] = e2;
            ps[s * PST + j0 + 3] = e3;
            const float* vp = vs + c0 + j0;
#pragma unroll
            for (int cc = 0; cc < 32; cc++) {
                float4 vv = *(const float4*)(vp + cc * WIN);
                o[cc] += e0 * vv.x + e1 * vv.y + e2 * vv.z + e3 * vv.w;
            }
        }
        __syncthreads();
#pragma unroll 8
        for (int k = 0; k < 32; k++) {
            int idx = s + k * 256;
            int row = idx >> 5, col = idx & 31;
            dout[abase + (size_t)row * WIN + c0 + col] = ps[row * PST + col];
        }
        __syncthreads();
    }

    float rinv = 1.0f / sum;
    rsum[s] = rinv;

    size_t obase = (size_t)b * C_SZ * PIX + p;
#pragma unroll
    for (int cc = 0; cc < 32; cc++) {
        float acc = lbsh[cc];
#pragma unroll
        for (int ky = 0; ky < 3; ky++) {
            int rr = rr0 + ky - 1;
            if (rr < 0 || rr >= hsp) continue;
#pragma unroll
            for (int kx = 0; kx < 3; kx++) {
                int cx = cc0 + kx - 1;
                if (cx < 0 || cx >= wsp) continue;
                acc += lwsh[cc][ky * 3 + kx] * vs[cc * WIN + rr * wsp + cx];
            }
        }
        int ch = br * 128 + cc * 4 + hd;
        xcat[obase + (size_t)ch * PIX] = o[cc] * rinv + acc;
    }
    __syncthreads();

    float4* ap = (float4*)(dout + abase);
#pragma unroll 4
    for (int k = 0; k < 64; k++) {
        int fidx = s + k * 256;
        float r = rsum[fidx >> 6];
        float4 v = ap[fidx];
        v.x *= r; v.y *= r; v.z *= r; v.w *= r;
        ap[fidx] = v;
    }
}

// ---------------------------------------------------------------------------
extern "C" void kernel_launch(void* const* d_in, const int* in_sizes, int n_in,
                              void* d_out, int out_size) {
    const float* x       = (const float*)d_in[0];
    const float* ln_g    = (const float*)d_in[1];
    const float* ln_b    = (const float*)d_in[2];
    const float* w_qkv   = (const float*)d_in[3];
    const float* proj_w  = (const float*)d_in[4];
    const float* proj_b  = (const float*)d_in[5];
    const float* lepe_w1 = (const float*)d_in[6];
    const float* lepe_b1 = (const float*)d_in[7];
    const float* lepe_w2 = (const float*)d_in[8];
    const float* lepe_b2 = (const float*)d_in[9];
    float* out = (float*)d_out;

    float *xn, *qkv, *xcat;
    cudaGetSymbolAddress((void**)&xn,   g_xn);
    cudaGetSymbolAddress((void**)&qkv,  g_qkv);
    cudaGetSymbolAddress((void**)&xcat, g_xcat);

    // 1. LayerNorm
    ln_kernel<<<L_TOT / 32, 256>>>(x, ln_g, ln_b, xn);

    // 2. QKV GEMM (tf32 tensor cores)
    {
        dim3 grid(L_TOT / 128, (3 * C_SZ) / 128);
        gemm_tf32<<<grid, 256>>>(xn, w_qkv, nullptr, qkv, C_SZ, 3 * C_SZ, 0);
    }

    // 3. Attention + LePE (both branches)
    {
        size_t dyn = (size_t)(64 * WIN + 256 * PST + 256) * sizeof(float);
        cudaFuncSetAttribute(attn_kernel, cudaFuncAttributeMaxDynamicSharedMemorySize,
                             (int)dyn);
        dim3 grid(NWIN, HEADS, 2);
        attn_kernel<<<grid, 256, dyn>>>(qkv, lepe_w1, lepe_b1, lepe_w2, lepe_b2,
                                        xcat, out);
    }

    // 4. Projection GEMM + bias (tf32 tensor cores) -> d_out[0 : OUT_ELEMS]
    {
        dim3 grid(L_TOT / 128, C_SZ / 128);
        gemm_tf32<<<grid, 256>>>(xcat, proj_w, proj_b, out, C_SZ, C_SZ, 1);
    }
    (void)in_sizes; (void)n_in; (void)out_size;
}

// round 4
// speedup vs baseline: 8.9867x; 1.5009x over previous
#include <cuda_runtime.h>
#include <math.h>
#include <stdint.h>

// Problem constants
#define B_SZ   8
#define C_SZ   256
#define H_SZ   64
#define W_SZ   64
#define PIX    4096          // H*W
#define L_TOT  32768         // B*H*W
#define HEADS  4
#define WIN    256           // window size (positions)
#define NWIN   128           // windows per branch (B*16)
#define SCALE  0.125f        // (256/4)^-0.5
#define LN_EPS 1e-4f

#define OUT_ELEMS  ((size_t)B_SZ * C_SZ * PIX)          // 8388608
#define ATTN_ELEMS ((size_t)NWIN * HEADS * WIN * WIN)   // 8388608

// Scratch (device globals — no allocation allowed)
__device__ float g_xn[(size_t)B_SZ * C_SZ * PIX];       // LayerNorm out, [b][c][p]
__device__ float g_qkv[(size_t)B_SZ * 3 * C_SZ * PIX];  // qkv, [b][j<768][p]
__device__ float g_xcat[(size_t)B_SZ * C_SZ * PIX];     // attention out, [b][c][p]

// ---------------------------------------------------------------------------
__device__ __forceinline__ uint32_t f2tf(float f) {
    uint32_t r;
    asm("cvt.rna.tf32.f32 %0, %1;" : "=r"(r) : "f"(f));
    return r;
}

__device__ __forceinline__ void mma_tf32(float* d, const uint32_t* a, const uint32_t* b) {
    asm("mma.sync.aligned.m16n8k8.row.col.f32.tf32.tf32.f32 "
        "{%0,%1,%2,%3},{%4,%5,%6,%7},{%8,%9},{%0,%1,%2,%3};"
        : "+f"(d[0]), "+f"(d[1]), "+f"(d[2]), "+f"(d[3])
        : "r"(a[0]), "r"(a[1]), "r"(a[2]), "r"(a[3]), "r"(b[0]), "r"(b[1]));
}

// ---------------------------------------------------------------------------
// LayerNorm over C for each pixel. Block = 32 pixels, 256 threads.
// ---------------------------------------------------------------------------
__global__ void ln_kernel(const float* __restrict__ x,
                          const float* __restrict__ g,
                          const float* __restrict__ be,
                          float* __restrict__ xnT) {
    int px0  = blockIdx.x * 32;
    int b    = px0 >> 12;
    int p0   = px0 & (PIX - 1);
    int lane = threadIdx.x & 31;
    int ty   = threadIdx.x >> 5;

    const float* xb = x + (size_t)b * C_SZ * PIX + p0 + lane;
    float v[32];
    float sum = 0.f, sq = 0.f;
#pragma unroll
    for (int i = 0; i < 32; i++) {
        int c = ty + i * 8;
        float t = xb[(size_t)c * PIX];
        v[i] = t;
        sum += t;
        sq  += t * t;
    }
    __shared__ float rs[2][8][32];
    __shared__ float mu_s[32], rstd_s[32];
    rs[0][ty][lane] = sum;
    rs[1][ty][lane] = sq;
    __syncthreads();
    if (ty == 0) {
        float s1 = 0.f, s2 = 0.f;
#pragma unroll
        for (int k = 0; k < 8; k++) { s1 += rs[0][k][lane]; s2 += rs[1][k][lane]; }
        float mu  = s1 * (1.0f / C_SZ);
        float var = s2 * (1.0f / C_SZ) - mu * mu;
        mu_s[lane]   = mu;
        rstd_s[lane] = rsqrtf(var + LN_EPS);
    }
    __syncthreads();
    float mu = mu_s[lane], rstd = rstd_s[lane];
    float* ob = xnT + (size_t)b * C_SZ * PIX + p0 + lane;
#pragma unroll
    for (int i = 0; i < 32; i++) {
        int c = ty + i * 8;
        ob[(size_t)c * PIX] = (v[i] - mu) * rstd * g[c] + be[c];
    }
}

// ---------------------------------------------------------------------------
// tf32 tensor-core GEMM with register-prefetch double buffering.
// outT[b][j][p] = sum_c AT[b][c][p] * W[j][c] (+bias)
// ---------------------------------------------------------------------------
#define ASTR 36
#define BSTR 132

__global__ __launch_bounds__(256, 2)
void gemm_tf32(const float* __restrict__ AT,
               const float* __restrict__ W,
               const float* __restrict__ bias,
               float* __restrict__ outT,
               int CA, int CO, int hasb) {
    __shared__ uint32_t As[128 * ASTR];   // [m][k]
    __shared__ uint32_t Bs[32 * BSTR];    // [k][n]

    int tid = threadIdx.x;
    int l0  = blockIdx.x * 128;
    int j0  = blockIdx.y * 128;
    int b   = l0 >> 12;
    int p0  = l0 & (PIX - 1);

    const float* Ab = AT + (size_t)b * CA * PIX + p0;
    int lane = tid & 31;
    int wid  = tid >> 5;
    int wm   = wid & 1;
    int wn   = wid >> 1;

    int aj  = tid >> 1;
    int ac  = (tid & 1) * 16;
    int bk  = tid >> 3;
    int bn7 = tid & 7;

    float d[4][4][4];
#pragma unroll
    for (int mt = 0; mt < 4; mt++)
#pragma unroll
        for (int nt = 0; nt < 4; nt++)
#pragma unroll
            for (int i = 0; i < 4; i++) d[mt][nt][i] = 0.f;

    // prologue: load chunk 0 into registers
    float4 awr[4], bwr[4];
    {
        const float* wrow = W + (size_t)(j0 + aj) * CA + ac;
        const float* arow = Ab + (size_t)bk * PIX;
#pragma unroll
        for (int i = 0; i < 4; i++) {
            awr[i] = *(const float4*)(wrow + 4 * i);
            bwr[i] = *(const float4*)(arow + (bn7 + 8 * i) * 4);
        }
    }

    for (int c0 = 0; c0 < CA; c0 += 32) {
        // store current regs (with tf32 cvt)
#pragma unroll
        for (int i = 0; i < 4; i++) {
            uint4 ua = make_uint4(f2tf(awr[i].x), f2tf(awr[i].y), f2tf(awr[i].z), f2tf(awr[i].w));
            *(uint4*)&As[aj * ASTR + ac + 4 * i] = ua;
            uint4 ub = make_uint4(f2tf(bwr[i].x), f2tf(bwr[i].y), f2tf(bwr[i].z), f2tf(bwr[i].w));
            *(uint4*)&Bs[bk * BSTR + (bn7 + 8 * i) * 4] = ub;
        }
        __syncthreads();

        // prefetch next chunk (hidden under MMA section)
        if (c0 + 32 < CA) {
            const float* wrow = W + (size_t)(j0 + aj) * CA + c0 + 32 + ac;
            const float* arow = Ab + (size_t)(c0 + 32 + bk) * PIX;
#pragma unroll
            for (int i = 0; i < 4; i++) {
                awr[i] = *(const float4*)(wrow + 4 * i);
                bwr[i] = *(const float4*)(arow + (bn7 + 8 * i) * 4);
            }
        }

#pragma unroll
        for (int ks = 0; ks < 4; ks++) {
            int kk = ks * 8 + (lane & 3);
            uint32_t afr[4][4], bfr[4][2];
#pragma unroll
            for (int mt = 0; mt < 4; mt++) {
                int m = wm * 64 + mt * 16 + (lane >> 2);
                afr[mt][0] = As[m * ASTR + kk];
                afr[mt][1] = As[(m + 8) * ASTR + kk];
                afr[mt][2] = As[m * ASTR + kk + 4];
                afr[mt][3] = As[(m + 8) * ASTR + kk + 4];
            }
#pragma unroll
            for (int nt = 0; nt < 4; nt++) {
                int n = wn * 32 + nt * 8 + (lane >> 2);
                bfr[nt][0] = Bs[kk * BSTR + n];
                bfr[nt][1] = Bs[(kk + 4) * BSTR + n];
            }
#pragma unroll
            for (int mt = 0; mt < 4; mt++)
#pragma unroll
                for (int nt = 0; nt < 4; nt++)
                    mma_tf32(d[mt][nt], afr[mt], bfr[nt]);
        }
        __syncthreads();
    }

    float* obase = outT + (size_t)b * CO * PIX;
#pragma unroll
    for (int mt = 0; mt < 4; mt++) {
        int j = j0 + wm * 64 + mt * 16 + (lane >> 2);
        float bv0 = hasb ? bias[j]     : 0.f;
        float bv1 = hasb ? bias[j + 8] : 0.f;
#pragma unroll
        for (int nt = 0; nt < 4; nt++) {
            int p = p0 + wn * 32 + nt * 8 + (lane & 3) * 2;
            float* o = obase + (size_t)j * PIX + p;
            *(float2*)o = make_float2(d[mt][nt][0] + bv0, d[mt][nt][1] + bv0);
            *(float2*)(o + 8 * PIX) = make_float2(d[mt][nt][2] + bv1, d[mt][nt][3] + bv1);
        }
    }
}

// ---------------------------------------------------------------------------
// MMA stripe-window attention + LePE.
// Block = one (branch, window, head). 8 warps; warp w owns query rows
// [32w, 32w+32). Loop over 8 key chunks of 32:
//   S = Q Kt (tf32 mma) -> exp(fp32) -> Es smem + gmem (unnormalized)
//   O += E V (tf32 mma)
// Row sums shuffle-reduced; O normalized in-register; O transposed via smem
// (reusing Ks) for LePE + xcat write; attn region normalized in a final pass.
// dyn smem: Qs/Es [256*36], Ks/Os [256*36], Vs [32*260], rsum[256] = ~105.5KB
// ---------------------------------------------------------------------------
#define QES 36
#define VST 260

__global__ __launch_bounds__(256, 2)
void attn_kernel(const float* __restrict__ qkvT,
                 const float* __restrict__ lw1,
                 const float* __restrict__ lb1,
                 const float* __restrict__ lw2,
                 const float* __restrict__ lb2,
                 float* __restrict__ xcat,
                 float* __restrict__ dout) {
    int br   = blockIdx.z;
    int hd   = blockIdx.y;
    int widx = blockIdx.x;
    int b    = widx >> 4;
    int wg   = widx & 15;
    int s    = threadIdx.x;
    int lane = s & 31;
    int w    = s >> 5;
    int r    = lane >> 2;     // 0..7
    int qk   = lane & 3;      // 0..3

    int hsp, wsp, p, rr0, cc0;
    if (br == 0) {                 // vertical stripes: 64 rows x 4 cols
        hsp = 64; wsp = 4;
        rr0 = s >> 2; cc0 = s & 3;
        p = rr0 * W_SZ + wg * 4 + cc0;
    } else {                       // horizontal stripes: 4 rows x 64 cols
        hsp = 4; wsp = 64;
        rr0 = s >> 6; cc0 = s & 63;
        p = (wg * 4 + rr0) * W_SZ + cc0;
    }
    const float* lw = br ? lw2 : lw1;
    const float* lb = br ? lb2 : lb1;

    extern __shared__ float sm[];
    float* Qs   = sm;                    // [256][36]  (becomes Es)
    float* Ks   = sm + 256 * QES;        // [256][36]  (becomes Os)
    float* Vs   = sm + 512 * QES;        // [32][260]
    float* rsum = Vs + 32 * VST;         // [256]
    __shared__ float lwsh[32][9];
    __shared__ float lbsh[32];

    // ---- load phase (coalesced LDG; STS conflicts acceptable, one-time) ----
    size_t base = (size_t)b * 3 * C_SZ * PIX;
#pragma unroll
    for (int cc = 0; cc < 32; cc++) {
        int ch = br * 128 + cc * 4 + hd;
        Qs[s * QES + cc]  = qkvT[base + (size_t)ch * PIX + p] * SCALE;
        Ks[s * QES + cc]  = qkvT[base + (size_t)(C_SZ + ch) * PIX + p];
        Vs[cc * VST + s]  = qkvT[base + (size_t)(2 * C_SZ + ch) * PIX + p];
    }
    for (int i = s; i < 32 * 9; i += 256) {
        int cc = i / 9, kk = i % 9;
        lwsh[cc][kk] = lw[(size_t)(cc * 4 + hd) * 9 + kk];
    }
    if (s < 32) lbsh[s] = lb[s * 4 + hd];
    __syncthreads();

    // ---- preload Q fragments (rows of this warp), tf32 ----
    uint32_t qf[2][4][4];    // [mt][ks][reg]
#pragma unroll
    for (int mt = 0; mt < 2; mt++) {
        int m0 = w * 32 + mt * 16 + r;
#pragma unroll
        for (int ks = 0; ks < 4; ks++) {
            int kk = ks * 8 + qk;
            qf[mt][ks][0] = f2tf(Qs[m0 * QES + kk]);
            qf[mt][ks][1] = f2tf(Qs[(m0 + 8) * QES + kk]);
            qf[mt][ks][2] = f2tf(Qs[m0 * QES + kk + 4]);
            qf[mt][ks][3] = f2tf(Qs[(m0 + 8) * QES + kk + 4]);
        }
    }
    __syncthreads();   // Qs now reusable as Es
    float* Es = Qs;

    size_t abase = OUT_ELEMS + (size_t)br * ATTN_ELEMS
                 + (size_t)(widx * HEADS + hd) * WIN * WIN;

    float oacc[2][4][4];
#pragma unroll
    for (int mt = 0; mt < 2; mt++)
#pragma unroll
        for (int nt = 0; nt < 4; nt++)
#pragma unroll
            for (int i = 0; i < 4; i++) oacc[mt][nt][i] = 0.f;
    float rsm[2][2] = {{0.f, 0.f}, {0.f, 0.f}};

    for (int c0 = 0; c0 < WIN; c0 += 32) {
        // ---- S = Q @ K^T for this chunk ----
        float sacc[2][4][4];
#pragma unroll
        for (int mt = 0; mt < 2; mt++)
#pragma unroll
            for (int nt = 0; nt < 4; nt++)
#pragma unroll
                for (int i = 0; i < 4; i++) sacc[mt][nt][i] = 0.f;

#pragma unroll
        for (int ks = 0; ks < 4; ks++) {
            int kk = ks * 8 + qk;
            uint32_t bf[4][2];
#pragma unroll
            for (int nt = 0; nt < 4; nt++) {
                int n = c0 + nt * 8 + r;
                bf[nt][0] = f2tf(Ks[n * QES + kk]);
                bf[nt][1] = f2tf(Ks[n * QES + kk + 4]);
            }
#pragma unroll
            for (int mt = 0; mt < 2; mt++)
#pragma unroll
                for (int nt = 0; nt < 4; nt++)
                    mma_tf32(sacc[mt][nt], qf[mt][ks], bf[nt]);
        }

        // ---- exp + row sums + stage E ----
#pragma unroll
        for (int mt = 0; mt < 2; mt++) {
            int m0 = w * 32 + mt * 16 + r;
#pragma unroll
            for (int nt = 0; nt < 4; nt++) {
                float e0 = __expf(sacc[mt][nt][0]);
                float e1 = __expf(sacc[mt][nt][1]);
                float e2 = __expf(sacc[mt][nt][2]);
                float e3 = __expf(sacc[mt][nt][3]);
                rsm[mt][0] += e0 + e1;
                rsm[mt][1] += e2 + e3;
                int col = nt * 8 + 2 * qk;
                *(float2*)&Es[m0 * QES + col]       = make_float2(e0, e1);
                *(float2*)&Es[(m0 + 8) * QES + col] = make_float2(e2, e3);
            }
        }
        __syncwarp();

        // ---- O += E @ V (each warp reads only its own E rows) ----
#pragma unroll
        for (int ks = 0; ks < 4; ks++) {
            int kk = ks * 8 + qk;
            uint32_t af[2][4], bv[4][2];
#pragma unroll
            for (int mt = 0; mt < 2; mt++) {
                int m0 = w * 32 + mt * 16 + r;
                af[mt][0] = f2tf(Es[m0 * QES + kk]);
                af[mt][1] = f2tf(Es[(m0 + 8) * QES + kk]);
                af[mt][2] = f2tf(Es[m0 * QES + kk + 4]);
                af[mt][3] = f2tf(Es[(m0 + 8) * QES + kk + 4]);
            }
#pragma unroll
            for (int nt = 0; nt < 4; nt++) {
                int ch = nt * 8 + r;
                bv[nt][0] = f2tf(Vs[ch * VST + c0 + kk]);
                bv[nt][1] = f2tf(Vs[ch * VST + c0 + kk + 4]);
            }
#pragma unroll
            for (int mt = 0; mt < 2; mt++)
#pragma unroll
                for (int nt = 0; nt < 4; nt++)
                    mma_tf32(oacc[mt][nt], af[mt], bv[nt]);
        }

        __syncthreads();
        // ---- coalesced unnormalized write of E chunk (256 x 32) ----
#pragma unroll
        for (int it = 0; it < 8; it++) {
            int f4 = s + it * 256;
            int row = f4 >> 3, c4 = f4 & 7;
            float4 v = *(float4*)&Es[row * QES + c4 * 4];
            *(float4*)&dout[abase + (size_t)row * WIN + c0 + c4 * 4] = v;
        }
        __syncthreads();
    }

    // ---- row-sum reduction + normalize O in registers ----
#pragma unroll
    for (int mt = 0; mt < 2; mt++)
#pragma unroll
        for (int j = 0; j < 2; j++) {
            float v = rsm[mt][j];
            v += __shfl_xor_sync(0xffffffffu, v, 1);
            v += __shfl_xor_sync(0xffffffffu, v, 2);
            rsm[mt][j] = 1.0f / v;
        }
#pragma unroll
    for (int mt = 0; mt < 2; mt++) {
        int m0 = w * 32 + mt * 16 + r;
        if (qk == 0) {
            rsum[m0]     = rsm[mt][0];
            rsum[m0 + 8] = rsm[mt][1];
        }
#pragma unroll
        for (int nt = 0; nt < 4; nt++) {
            oacc[mt][nt][0] *= rsm[mt][0];
            oacc[mt][nt][1] *= rsm[mt][0];
            oacc[mt][nt][2] *= rsm[mt][1];
            oacc[mt][nt][3] *= rsm[mt][1];
        }
    }

    // ---- transpose O via smem (reuse Ks as Os[32][VST]) ----
    float* Os = Ks;
#pragma unroll
    for (int mt = 0; mt < 2; mt++) {
        int m0 = w * 32 + mt * 16 + r;
#pragma unroll
        for (int nt = 0; nt < 4; nt++) {
            int ch = nt * 8 + 2 * qk;
            Os[ch * VST + m0]           = oacc[mt][nt][0];
            Os[(ch + 1) * VST + m0]     = oacc[mt][nt][1];
            Os[ch * VST + m0 + 8]       = oacc[mt][nt][2];
            Os[(ch + 1) * VST + m0 + 8] = oacc[mt][nt][3];
        }
    }
    __syncthreads();

    // ---- LePE + output to xcat ----
    size_t obase = (size_t)b * C_SZ * PIX + p;
#pragma unroll
    for (int cc = 0; cc < 32; cc++) {
        float acc = lbsh[cc];
#pragma unroll
        for (int ky = 0; ky < 3; ky++) {
            int rr = rr0 + ky - 1;
            if (rr < 0 || rr >= hsp) continue;
#pragma unroll
            for (int kx = 0; kx < 3; kx++) {
                int cx = cc0 + kx - 1;
                if (cx < 0 || cx >= wsp) continue;
                acc += lwsh[cc][ky * 3 + kx] * Vs[cc * VST + rr * wsp + cx];
            }
        }
        int ch = br * 128 + cc * 4 + hd;
        xcat[obase + (size_t)ch * PIX] = Os[cc * VST + s] + acc;
    }

    // ---- normalize attn region (L2-resident) ----
    float4* ap = (float4*)(dout + abase);
#pragma unroll 4
    for (int k = 0; k < 64; k++) {
        int fidx = s + k * 256;
        float rv = rsum[fidx >> 6];
        float4 v = ap[fidx];
        v.x *= rv; v.y *= rv; v.z *= rv; v.w *= rv;
        ap[fidx] = v;
    }
}

// ---------------------------------------------------------------------------
extern "C" void kernel_launch(void* const* d_in, const int* in_sizes, int n_in,
                              void* d_out, int out_size) {
    const float* x       = (const float*)d_in[0];
    const float* ln_g    = (const float*)d_in[1];
    const float* ln_b    = (const float*)d_in[2];
    const float* w_qkv   = (const float*)d_in[3];
    const float* proj_w  = (const float*)d_in[4];
    const float* proj_b  = (const float*)d_in[5];
    const float* lepe_w1 = (const float*)d_in[6];
    const float* lepe_b1 = (const float*)d_in[7];
    const float* lepe_w2 = (const float*)d_in[8];
    const float* lepe_b2 = (const float*)d_in[9];
    float* out = (float*)d_out;

    float *xn, *qkv, *xcat;
    cudaGetSymbolAddress((void**)&xn,   g_xn);
    cudaGetSymbolAddress((void**)&qkv,  g_qkv);
    cudaGetSymbolAddress((void**)&xcat, g_xcat);

    // 1. LayerNorm
    ln_kernel<<<L_TOT / 32, 256>>>(x, ln_g, ln_b, xn);

    // 2. QKV GEMM (tf32 tensor cores)
    {
        dim3 grid(L_TOT / 128, (3 * C_SZ) / 128);
        gemm_tf32<<<grid, 256>>>(xn, w_qkv, nullptr, qkv, C_SZ, 3 * C_SZ, 0);
    }

    // 3. Attention + LePE (both branches), tf32 MMA
    {
        size_t dyn = (size_t)(512 * QES + 32 * VST + 256) * sizeof(float);
        cudaFuncSetAttribute(attn_kernel, cudaFuncAttributeMaxDynamicSharedMemorySize,
                             (int)dyn);
        dim3 grid(NWIN, HEADS, 2);
        attn_kernel<<<grid, 256, dyn>>>(qkv, lepe_w1, lepe_b1, lepe_w2, lepe_b2,
                                        xcat, out);
    }

    // 4. Projection GEMM + bias (tf32) -> d_out[0 : OUT_ELEMS]
    {
        dim3 grid(L_TOT / 128, C_SZ / 128);
        gemm_tf32<<<grid, 256>>>(xcat, proj_w, proj_b, out, C_SZ, C_SZ, 1);
    }
    (void)in_sizes; (void)n_in; (void)out_size;
}